// round 16
// baseline (speedup 1.0000x reference)
#include <cuda_runtime.h>
#include <cuda_fp16.h>
#include <cstdint>

// ---------------------------------------------------------------------------
// SmallMLP_INR: fused 6-layer MLP, base-target ISA (compute_103-safe).
// fp16 m16n8k16 mma.sync + ldmatrix, persistent CTAs, flag-gated warp skew
// (R13+R15 wins). NEW: layer 1 of tile T+1 is computed during tile T's
// layer-5 MMAs (sA0 free after layer 4), all sync via MONOTONIC release/
// acquire counters -> 1 CTA barrier per tile (layer-6 reduce) instead of 3.
// ---------------------------------------------------------------------------

#define THREADS 256
#define TILE_M  128
#define KDIM    256
#define NDIM    256

#define A_STRIDE 264       // halves; 528B rows -> ldmatrix conflict-free
#define SLOT_BYTES 4096    // 32 n-rows * 128B (64 k halves), XOR-swizzled
#define WARP_RING  8192    // 2 slots

// SMEM layout (bytes)
#define SM_W1    0
#define SM_B1    2048
#define SM_B2    3072
#define SM_B3    4096
#define SM_B4    5120
#define SM_B5    6144
#define SM_W6    7168
#define SM_B6    8192
#define SM_FLAGS 8208     // flagE[3][4]=12, rdDone[3], l1done = 16 ints
#define SM_PART  8272     // 8*128 f32 = 4096
#define SM_A0    12416    // 128*264*2 = 67584
#define SM_A1    80000    // 67584
#define SM_RING  147584   // 8 warps * 8192 = 65536
#define SMEM_TOTAL 213120

// flag indices (ints)
#define FG_E(l, c)  ((l) * 4 + (c))
#define FG_RD(l)    (12 + (l))
#define FG_L1       15

// Pre-transposed fp16 weights: g_WtH[l][n*256 + k] = (half)W_{l+2}[k][n]
__device__ __half g_WtH[4][KDIM * NDIM];

// ---------------------------------------------------------------------------
__device__ __forceinline__ uint32_t smem_u32(const void* p) {
    uint32_t a;
    asm("{ .reg .u64 t; cvta.to.shared.u64 t, %1; cvt.u32.u64 %0, t; }" : "=r"(a) : "l"(p));
    return a;
}

__device__ __forceinline__ void mma_f16(float* c, const uint32_t* a, const uint32_t* b) {
    asm volatile(
        "mma.sync.aligned.m16n8k16.row.col.f32.f16.f16.f32 "
        "{%0,%1,%2,%3}, {%4,%5,%6,%7}, {%8,%9}, {%0,%1,%2,%3};\n"
        : "+f"(c[0]), "+f"(c[1]), "+f"(c[2]), "+f"(c[3])
        : "r"(a[0]), "r"(a[1]), "r"(a[2]), "r"(a[3]), "r"(b[0]), "r"(b[1]));
}

#define LDMATRIX_X4(r0, r1, r2, r3, addr) \
    asm volatile("ldmatrix.sync.aligned.m8n8.x4.shared.b16 {%0,%1,%2,%3}, [%4];" \
                 : "=r"(r0), "=r"(r1), "=r"(r2), "=r"(r3) : "r"(addr))

__device__ __forceinline__ void cp_async16(uint32_t dst, const void* src) {
    asm volatile("cp.async.cg.shared.global [%0], [%1], 16;" :: "r"(dst), "l"(src) : "memory");
}
__device__ __forceinline__ void cp_commit() { asm volatile("cp.async.commit_group;" ::: "memory"); }
__device__ __forceinline__ void cp_wait1()  { asm volatile("cp.async.wait_group 1;" ::: "memory"); }
__device__ __forceinline__ void cp_wait0()  { asm volatile("cp.async.wait_group 0;" ::: "memory"); }

// release/acquire flag ops (CTA scope, shared memory), monotonic counters
__device__ __forceinline__ int ld_acq(uint32_t a) {
    int v;
    asm volatile("ld.acquire.cta.shared.b32 %0, [%1];" : "=r"(v) : "r"(a) : "memory");
    return v;
}
__device__ __forceinline__ void red_rel(uint32_t a) {
    asm volatile("red.release.cta.shared.add.u32 [%0], %1;" :: "r"(a), "r"(1) : "memory");
}
__device__ __forceinline__ void spin_ge(uint32_t a, int target) {
    while (ld_acq(a) < target) { }
}

// Warp-private: one 32n x 64k B chunk (4KB) into a ring slot.
__device__ __forceinline__ void load_wchunk(uint32_t slot, const __half* Wt,
                                            int nbase, int c, int lid) {
    const uint32_t dst = slot + (uint32_t)lid * 128;
    const uint32_t rx = (uint32_t)(lid & 7);
    const __half* src = Wt + (size_t)(nbase + lid) * KDIM + c * 64;
#pragma unroll
    for (uint32_t j = 0; j < 8; j++)
        cp_async16(dst + ((j ^ rx) << 4), src + j * 8);
    cp_commit();
}

// ---------------------------------------------------------------------------
// weight pre-transpose + fp16 round
// ---------------------------------------------------------------------------
__global__ void transpose_w_kernel(const float* __restrict__ W2, const float* __restrict__ W3,
                                   const float* __restrict__ W4, const float* __restrict__ W5) {
    __shared__ float t[32][33];
    const float* W = (blockIdx.z == 0) ? W2 : (blockIdx.z == 1) ? W3
                   : (blockIdx.z == 2) ? W4 : W5;
    const int nb = blockIdx.x * 32, kb = blockIdx.y * 32;
    const int tx = threadIdx.x, ty = threadIdx.y;
#pragma unroll
    for (int i = 0; i < 32; i += 8)
        t[ty + i][tx] = W[(size_t)(kb + ty + i) * 256 + (nb + tx)];
    __syncthreads();
    __half* dst = g_WtH[blockIdx.z];
#pragma unroll
    for (int i = 0; i < 32; i += 8)
        dst[(size_t)(nb + ty + i) * 256 + (kb + tx)] = __float2half_rn(t[tx][ty + i]);
}

// ---------------------------------------------------------------------------
// main persistent kernel
// ---------------------------------------------------------------------------
__global__ void __launch_bounds__(THREADS, 1) mlp_kernel(
    const float* __restrict__ coords,
    const float* __restrict__ W1, const float* __restrict__ b1,
    const float* __restrict__ b2, const float* __restrict__ b3,
    const float* __restrict__ b4, const float* __restrict__ b5,
    const float* __restrict__ W6, const float* __restrict__ b6,
    float* __restrict__ out, int ntiles) {
    extern __shared__ __align__(128) char smem[];
    const uint32_t sb = smem_u32(smem);
    const int tid = threadIdx.x;
    const int wid = tid >> 5;
    const int lid = tid & 31;
    const int g = lid >> 2;
    const int t = lid & 3;
    const int nbase = wid * 32;      // this warp's private N slice

    float* sW1 = (float*)(smem + SM_W1);
    float* sB1 = (float*)(smem + SM_B1);
    float* sB2 = (float*)(smem + SM_B2);
    float* sB3 = (float*)(smem + SM_B3);
    float* sB4 = (float*)(smem + SM_B4);
    float* sB5 = (float*)(smem + SM_B5);
    float* sW6 = (float*)(smem + SM_W6);
    float* sB6 = (float*)(smem + SM_B6);
    float* sPart = (float*)(smem + SM_PART);
    __half* sA0 = (__half*)(smem + SM_A0);
    __half* sA1 = (__half*)(smem + SM_A1);
    const uint32_t fbase = sb + SM_FLAGS;
    const uint32_t ring = sb + SM_RING + (uint32_t)wid * WARP_RING;

    // stage small params
    sW1[tid]       = W1[tid];
    sW1[tid + 256] = W1[tid + 256];
    sB1[tid] = b1[tid];
    sB2[tid] = b2[tid];
    sB3[tid] = b3[tid];
    sB4[tid] = b4[tid];
    sB5[tid] = b5[tid];
    sW6[tid] = W6[tid];
    if (tid == 0) sB6[0] = b6[0];
    if (tid < 16) *(int*)(smem + SM_FLAGS + tid * 4) = 0;

    // prologue: warp prefetches its chunks 0,1 of layer 2 (slots 0,1)
    load_wchunk(ring,              g_WtH[0], nbase, 0, lid);
    load_wchunk(ring + SLOT_BYTES, g_WtH[0], nbase, 1, lid);

    __syncthreads();

    // ---- layer 1 of this CTA's FIRST tile -> sA0 ----
    {
        const int row = tid >> 1;
        const int j0  = (tid & 1) * 128;
        const float2 c = *(const float2*)(coords +
                         2 * (size_t)(blockIdx.x * TILE_M + row));
        __half* dst = sA0 + (size_t)row * A_STRIDE;
#pragma unroll
        for (int j = 0; j < 128; j += 2) {
            const int jj = j0 + j;
            float v0 = fmaxf(fmaf(c.x, sW1[jj + 0], fmaf(c.y, sW1[256 + jj + 0], sB1[jj + 0])), 0.f);
            float v1 = fmaxf(fmaf(c.x, sW1[jj + 1], fmaf(c.y, sW1[256 + jj + 1], sB1[jj + 1])), 0.f);
            *(__half2*)(dst + jj) = __floats2half2_rn(v0, v1);
        }
    }
    __syncwarp();
    if (lid == 0) red_rel(fbase + FG_L1 * 4);

    // ldmatrix lane-address bases
    const uint32_t aOff =
        (uint32_t)(((lid & 15) * A_STRIDE + ((lid & 16) ? 8 : 0)) * 2);
    const uint32_t aA0 = sb + SM_A0 + aOff;
    const uint32_t aA1 = sb + SM_A1 + aOff;
    const int brow = (lid & 7) + ((lid & 16) ? 8 : 0);
    const uint32_t bRow = (uint32_t)brow * 128;
    const uint32_t brx = (uint32_t)(brow & 7);
    const uint32_t b8 = (uint32_t)((lid >> 3) & 1);

    const int stride = gridDim.x;
    int iter = 0;

#pragma unroll 1
    for (int tile = blockIdx.x; tile < ntiles; tile += stride, iter++) {
        const bool lastT = (tile + stride >= ntiles);
        const int row_base = tile * TILE_M;

        // ---- Layers 2..5: counter-gated, warps skew freely ----
#pragma unroll 1
        for (int l = 0; l < 4; l++) {
            float acc[8][4][4];
#pragma unroll
            for (int i = 0; i < 8; i++)
#pragma unroll
                for (int j = 0; j < 4; j++)
#pragma unroll
                    for (int c = 0; c < 4; c++) acc[i][j][c] = 0.f;

            const uint32_t aA = (l & 1) ? aA1 : aA0;

#pragma unroll
            for (int c = 0; c < 4; c++) {
                const int f = l * 4 + c;

                // gate A availability
                if (l == 0) {
                    if (c == 0) spin_ge(fbase + FG_L1 * 4, 8 * (iter + 1));
                } else {
                    spin_ge(fbase + FG_E(l - 1, c) * 4, 2 * (iter + 1));
                }

                // B chunk f arrival (warp-private ring)
                if (lastT && f == 15) cp_wait0(); else cp_wait1();
                __syncwarp();

                const uint32_t slot = ring + (uint32_t)(f & 1) * SLOT_BYTES;
#pragma unroll
                for (int ks = 0; ks < 4; ks++) {
                    const int k0 = c * 64 + ks * 16;
                    const uint32_t soff = ((((uint32_t)(2 * ks) + b8) ^ brx) << 4);
                    uint32_t b[2][4];
#pragma unroll
                    for (int np = 0; np < 2; np++)
                        LDMATRIX_X4(b[np][0], b[np][1], b[np][2], b[np][3],
                                    slot + bRow + (uint32_t)np * 2048 + soff);
#pragma unroll
                    for (int i = 0; i < 8; i++) {
                        uint32_t a[4];
                        LDMATRIX_X4(a[0], a[1], a[2], a[3],
                                    aA + (uint32_t)(i * 16 * A_STRIDE + k0) * 2);
#pragma unroll
                        for (int j = 0; j < 4; j++)
                            mma_f16(acc[i][j], a, &b[j >> 1][(j & 1) * 2]);
                    }
                }

                // prefetch flat chunk f+2 into the slot just consumed
                if (!(lastT && f >= 14)) {
                    const int q = f + 2;
                    load_wchunk(ring + (uint32_t)(q & 1) * SLOT_BYTES,
                                g_WtH[(q >> 2) & 3], nbase, q & 3, lid);
                }
            }

            // this warp done reading buf[l&1] this tile (l=0,1,2 have waiters)
            if (l < 3 && lid == 0) red_rel(fbase + FG_RD(l) * 4);

            if (l < 3) {
                // WAR gate: buf[(l+1)&1] free once all warps read it in l-1
                if (l >= 1) spin_ge(fbase + FG_RD(l - 1) * 4, 8 * (iter + 1));

                // epilogue: buf[(l+1)&1] <- (half)relu(D + bias)
                __half* sAW = ((l + 1) & 1) ? sA1 : sA0;
                const float* bias = (l == 0) ? sB2 : (l == 1) ? sB3 : sB4;
#pragma unroll
                for (int j = 0; j < 4; j++) {
                    const int col = nbase + 8 * j + 2 * t;
                    const float bs0 = bias[col], bs1 = bias[col + 1];
#pragma unroll
                    for (int i = 0; i < 8; i++) {
                        const int row = 16 * i + g;
                        *(__half2*)(sAW + (size_t)row * A_STRIDE + col) =
                            __floats2half2_rn(fmaxf(acc[i][j][0] + bs0, 0.f),
                                              fmaxf(acc[i][j][1] + bs1, 0.f));
                        *(__half2*)(sAW + (size_t)(row + 8) * A_STRIDE + col) =
                            __floats2half2_rn(fmaxf(acc[i][j][2] + bs0, 0.f),
                                              fmaxf(acc[i][j][3] + bs1, 0.f));
                    }
                }
                __syncwarp();
                if (lid == 0) red_rel(fbase + FG_E(l, wid >> 1) * 4);
            } else {
                // ---- Layer 6: out = relu(D + b5) . W6 + b6 ----
                float r0[8], r1[8];
#pragma unroll
                for (int i = 0; i < 8; i++) { r0[i] = 0.f; r1[i] = 0.f; }
#pragma unroll
                for (int j = 0; j < 4; j++) {
                    const int col = nbase + 8 * j + 2 * t;
                    const float w0 = sW6[col], w1 = sW6[col + 1];
                    const float s0 = sB5[col], s1 = sB5[col + 1];
#pragma unroll
                    for (int i = 0; i < 8; i++) {
                        r0[i] = fmaf(fmaxf(acc[i][j][0] + s0, 0.f), w0, r0[i]);
                        r0[i] = fmaf(fmaxf(acc[i][j][1] + s1, 0.f), w1, r0[i]);
                        r1[i] = fmaf(fmaxf(acc[i][j][2] + s0, 0.f), w0, r1[i]);
                        r1[i] = fmaf(fmaxf(acc[i][j][3] + s1, 0.f), w1, r1[i]);
                    }
                }
#pragma unroll
                for (int d = 1; d <= 2; d <<= 1) {
#pragma unroll
                    for (int i = 0; i < 8; i++) {
                        r0[i] += __shfl_xor_sync(0xFFFFFFFFu, r0[i], d);
                        r1[i] += __shfl_xor_sync(0xFFFFFFFFu, r1[i], d);
                    }
                }
                if (t == 0) {
                    float* part = sPart + wid * 128;
#pragma unroll
                    for (int i = 0; i < 8; i++) {
                        part[16 * i + g]     = r0[i];
                        part[16 * i + g + 8] = r1[i];
                    }
                }

                // ---- overlapped: NEXT tile's layer 1 -> sA0 ----
                // sA0 last read at l=2; all warps being >= l=3 means
                // rdDone[2] hit this tile's target.
                if (!lastT) {
                    spin_ge(fbase + FG_RD(2) * 4, 8 * (iter + 1));
                    const int row = tid >> 1;
                    const int j0  = (tid & 1) * 128;
                    const float2 c = *(const float2*)(coords +
                        2 * (size_t)((tile + stride) * TILE_M + row));
                    __half* dst = sA0 + (size_t)row * A_STRIDE;
#pragma unroll
                    for (int j = 0; j < 128; j += 2) {
                        const int jj = j0 + j;
                        float v0 = fmaxf(fmaf(c.x, sW1[jj + 0],
                                   fmaf(c.y, sW1[256 + jj + 0], sB1[jj + 0])), 0.f);
                        float v1 = fmaxf(fmaf(c.x, sW1[jj + 1],
                                   fmaf(c.y, sW1[256 + jj + 1], sB1[jj + 1])), 0.f);
                        *(__half2*)(dst + jj) = __floats2half2_rn(v0, v1);
                    }
                    __syncwarp();
                    if (lid == 0) red_rel(fbase + FG_L1 * 4);
                }

                // single CTA barrier per tile: sPart complete AND all warps
                // past their l=3 MMAs (sA1 safe for next tile's l=0 epilogue)
                __syncthreads();
                if (tid < TILE_M) {
                    float s = sB6[0];
#pragma unroll
                    for (int w = 0; w < 8; w++) s += sPart[w * 128 + tid];
                    out[row_base + tid] = s;
                }
            }
        }
    }
}

// ---------------------------------------------------------------------------
extern "C" void kernel_launch(void* const* d_in, const int* in_sizes, int n_in,
                              void* d_out, int out_size) {
    const float* coords = (const float*)d_in[0];
    const float* W1 = (const float*)d_in[1];
    const float* b1 = (const float*)d_in[2];
    const float* W2 = (const float*)d_in[3];
    const float* b2 = (const float*)d_in[4];
    const float* W3 = (const float*)d_in[5];
    const float* b3 = (const float*)d_in[6];
    const float* W4 = (const float*)d_in[7];
    const float* b4 = (const float*)d_in[8];
    const float* W5 = (const float*)d_in[9];
    const float* b5 = (const float*)d_in[10];
    const float* W6 = (const float*)d_in[11];
    const float* b6 = (const float*)d_in[12];
    float* out = (float*)d_out;

    const int n = in_sizes[0] / 2;      // rows
    const int ntiles = n / TILE_M;      // 4096

    int nsm = 148;
    cudaDeviceGetAttribute(&nsm, cudaDevAttrMultiProcessorCount, 0);
    const int grid = (nsm < ntiles) ? nsm : ntiles;

    transpose_w_kernel<<<dim3(NDIM / 32, KDIM / 32, 4), dim3(32, 8)>>>(W2, W3, W4, W5);

    cudaFuncSetAttribute(mlp_kernel, cudaFuncAttributeMaxDynamicSharedMemorySize, SMEM_TOTAL);
    mlp_kernel<<<grid, THREADS, SMEM_TOTAL>>>(coords, W1, b1, b2, b3, b4, b5,
                                              W6, b6, out, ntiles);
}